// round 5
// baseline (speedup 1.0000x reference)
#include <cuda_runtime.h>

#define BB 8
#define CC 64
#define HWSZ (512*512)
#define NPIX (BB*HWSZ)      // 2097152
#define K 19
#define NT 256
#define CHUNKS 37

__device__ float         g_sums[CC * K];     // [c][k]
__device__ unsigned int  g_counts[K];
__device__ unsigned int  g_ticket;
__device__ unsigned char g_tgt[NPIX];

// ---------------- targets int32 -> uint8 + histogram ----------------
__global__ void __launch_bounds__(256) prep_kernel(const int* __restrict__ tgt) {
    __shared__ unsigned int hist[K];
    if (threadIdx.x < K) hist[threadIdx.x] = 0u;
    __syncthreads();

    int idx = blockIdx.x * blockDim.x + threadIdx.x;   // group of 8 pixels
    const int4* tv = (const int4*)tgt;
    int4 a = tv[idx * 2];
    int4 b = tv[idx * 2 + 1];
    int t[8] = {a.x, a.y, a.z, a.w, b.x, b.y, b.z, b.w};

    unsigned long long packed = 0ull;
#pragma unroll
    for (int j = 0; j < 8; j++) {
        atomicAdd(&hist[t[j]], 1u);
        packed |= ((unsigned long long)((unsigned int)t[j] & 0xFFu)) << (8 * j);
    }
    ((unsigned long long*)g_tgt)[idx] = packed;

    __syncthreads();
    if (threadIdx.x < K) atomicAdd(&g_counts[threadIdx.x], hist[threadIdx.x]);
}

// ---------------- fused accumulate + finalize ----------------
// grid = (CHUNKS, CC). Block handles channel blockIdx.y, pixel chunk blockIdx.x.
// Each thread owns a private conflict-free smem column of K accumulators:
//   addr word = k*NT + tid  ->  bank = tid % 32 (independent of k) -> 0 conflicts.
// Inner loop deliberately simple (R3 form): plain float4 LDG, no unroll pragma,
// no cache-policy override — ptxas schedules the independent iterations with
// enough MLP to run at ~85% of DRAM spec.
__global__ void __launch_bounds__(NT) acc_kernel(const float* __restrict__ in,
                                                 float* __restrict__ out) {
    __shared__ float sums[K * NT];
    const int tid = threadIdx.x;
#pragma unroll
    for (int k = 0; k < K; k++) sums[k * NT + tid] = 0.0f;
    __syncthreads();

    const int c = blockIdx.y;
    const int NV = NPIX / 4;                 // float4 groups
    for (int g = blockIdx.x * NT + tid; g < NV; g += CHUNKS * NT) {
        int p  = g * 4;
        int b  = p >> 18;                    // p / HWSZ
        int hw = p & (HWSZ - 1);
        const float4 x = *(const float4*)(in + ((long)(b * CC + c)) * HWSZ + hw);
        uchar4 t4 = ((const uchar4*)g_tgt)[g];
        sums[(int)t4.x * NT + tid] += x.x;
        sums[(int)t4.y * NT + tid] += x.y;
        sums[(int)t4.z * NT + tid] += x.z;
        sums[(int)t4.w * NT + tid] += x.w;
    }
    __syncthreads();

    // block reduction: warp w handles classes w, w+8, ...
    const int warp = tid >> 5, lane = tid & 31;
    for (int k = warp; k < K; k += NT / 32) {
        float v = 0.0f;
#pragma unroll
        for (int j = 0; j < NT / 32; j++) v += sums[k * NT + j * 32 + lane];
#pragma unroll
        for (int o = 16; o > 0; o >>= 1) v += __shfl_xor_sync(0xFFFFFFFFu, v, o);
        if (lane == 0) atomicAdd(&g_sums[c * K + k], v);
    }

    // ---- last-block finalize ----
    __threadfence();
    __shared__ unsigned int is_last;
    if (tid == 0) {
        unsigned int t = atomicAdd(&g_ticket, 1u);
        is_last = (t == CHUNKS * CC - 1) ? 1u : 0u;
    }
    __syncthreads();
    if (!is_last) return;

    // reuse smem: cn[K][CC] (4864B) + inv_norm + acc fit inside sums[]
    float (*cn)[CC]  = (float (*)[CC])sums;
    float* inv_norm  = sums + K * CC;
    float* accp      = sums + K * CC + K;
    if (tid == 0) *accp = 0.0f;

    for (int i = tid; i < K * CC; i += NT) {
        int k = i / CC, ch = i % CC;
        float cnt = (float)g_counts[k];
        if (cnt < 1.0f) cnt = 1.0f;
        cn[k][ch] = g_sums[ch * K + k] / cnt;
    }
    __syncthreads();

    if (tid < K) {
        float s = 0.0f;
#pragma unroll
        for (int ch = 0; ch < CC; ch++) { float v = cn[tid][ch]; s += v * v; }
        float n = sqrtf(s);
        if (n < 1e-8f) n = 1e-8f;
        inv_norm[tid] = 1.0f / n;
    }
    __syncthreads();

    for (int i = tid; i < K * CC; i += NT) {
        int k = i / CC;
        cn[k][i % CC] *= inv_norm[k];
    }
    __syncthreads();

    float local = 0.0f;
    for (int pair = tid; pair < K * K; pair += NT) {
        int i = pair / K, j = pair % K;
        float s = 0.0f;
#pragma unroll
        for (int ch = 0; ch < CC; ch++) s += cn[i][ch] * cn[j][ch];
        local += (i == j) ? (1.0f - s) : fmaxf(s, 0.0f);
    }
#pragma unroll
    for (int o = 16; o > 0; o >>= 1) local += __shfl_xor_sync(0xFFFFFFFFu, local, o);
    if (lane == 0) atomicAdd(accp, local);
    __syncthreads();
    if (tid == 0) *out = *accp / (float)(K * K * K);

    // ---- self-reset scratch for the next launch ----
    for (int i = tid; i < CC * K; i += NT) g_sums[i] = 0.0f;
    if (tid < K) g_counts[tid] = 0u;
    if (tid == 0) g_ticket = 0u;
}

extern "C" void kernel_launch(void* const* d_in, const int* in_sizes, int n_in,
                              void* d_out, int out_size) {
    const float* in  = (const float*)d_in[0];
    const int*   tgt = (const int*)d_in[1];
    float*       out = (float*)d_out;

    prep_kernel<<<NPIX / 8 / 256, 256>>>(tgt);
    acc_kernel<<<dim3(CHUNKS, CC), NT>>>(in, out);
}

// round 6
// speedup vs baseline: 1.3455x; 1.3455x over previous
#include <cuda_runtime.h>

#define BB 8
#define CC 64
#define HWSZ (512*512)
#define NPIX (BB*HWSZ)      // 2097152
#define K 19
#define NT 256
#define CHUNKS 37
#define KP 20                // padded K for bank-spread histogram replicas

__device__ float         g_sums[CC * K];     // [c][k]
__device__ unsigned int  g_counts[K];
__device__ unsigned char g_tgt[NPIX];

// ---------------- targets int32 -> uint8 + histogram ----------------
// 8-way replicated smem histogram (stride KP=20 words -> replicas live in
// distinct banks for a given class) cuts same-address ATOMS conflicts ~8x.
__global__ void __launch_bounds__(256) prep_kernel(const int* __restrict__ tgt) {
    __shared__ unsigned int hist[8 * KP];
    for (int i = threadIdx.x; i < 8 * KP; i += 256) hist[i] = 0u;
    __syncthreads();

    const int sub = threadIdx.x & 7;
    int idx = blockIdx.x * blockDim.x + threadIdx.x;   // group of 8 pixels
    const int4* tv = (const int4*)tgt;
    int4 a = tv[idx * 2];
    int4 b = tv[idx * 2 + 1];
    int t[8] = {a.x, a.y, a.z, a.w, b.x, b.y, b.z, b.w};

    unsigned long long packed = 0ull;
#pragma unroll
    for (int j = 0; j < 8; j++) {
        atomicAdd(&hist[sub * KP + t[j]], 1u);
        packed |= ((unsigned long long)((unsigned int)t[j] & 0xFFu)) << (8 * j);
    }
    ((unsigned long long*)g_tgt)[idx] = packed;

    __syncthreads();
    if (threadIdx.x < K) {
        unsigned int s = 0u;
#pragma unroll
        for (int r = 0; r < 8; r++) s += hist[r * KP + threadIdx.x];
        atomicAdd(&g_counts[threadIdx.x], s);
    }
}

// ---------------- main accumulate: per-class per-channel sums ----------------
// grid = (CHUNKS, CC). Block handles channel blockIdx.y, pixel chunk blockIdx.x.
// Each thread owns a private conflict-free smem column of K accumulators:
//   addr word = k*NT + tid  ->  bank = tid % 32 (independent of k) -> 0 conflicts.
// Loop kept in the exact R3 form that measured ~79us (plain float4 LDG, no
// pragma, no cache hints) — ptxas schedules enough MLP to run near DRAM cap.
__global__ void __launch_bounds__(NT) acc_kernel(const float* __restrict__ in) {
    __shared__ float sums[K * NT];
    const int tid = threadIdx.x;
#pragma unroll
    for (int k = 0; k < K; k++) sums[k * NT + tid] = 0.0f;
    __syncthreads();

    const int c = blockIdx.y;
    const int NV = NPIX / 4;                 // float4 groups
    for (int g = blockIdx.x * NT + tid; g < NV; g += CHUNKS * NT) {
        int p  = g * 4;
        int b  = p >> 18;                    // p / HWSZ
        int hw = p & (HWSZ - 1);
        const float4 x = *(const float4*)(in + ((long)(b * CC + c)) * HWSZ + hw);
        uchar4 t4 = ((const uchar4*)g_tgt)[g];
        sums[(int)t4.x * NT + tid] += x.x;
        sums[(int)t4.y * NT + tid] += x.y;
        sums[(int)t4.z * NT + tid] += x.z;
        sums[(int)t4.w * NT + tid] += x.w;
    }
    __syncthreads();

    // block reduction: warp w handles classes w, w+8, ...
    const int warp = tid >> 5, lane = tid & 31;
    for (int k = warp; k < K; k += NT / 32) {
        float v = 0.0f;
#pragma unroll
        for (int j = 0; j < NT / 32; j++) v += sums[k * NT + j * 32 + lane];
#pragma unroll
        for (int o = 16; o > 0; o >>= 1) v += __shfl_xor_sync(0xFFFFFFFFu, v, o);
        if (lane == 0) atomicAdd(&g_sums[c * K + k], v);
    }
}

// ---------------- finalize: centroids -> cosine loss scalar ----------------
// Also self-resets g_sums/g_counts so the next graph replay starts clean
// (replaces the standalone zero_kernel).
__global__ void __launch_bounds__(256) finalize_kernel(float* __restrict__ out) {
    __shared__ float cn[K][CC];
    __shared__ float inv_norm[K];
    __shared__ float acc;
    const int tid = threadIdx.x;
    const int lane = tid & 31;
    if (tid == 0) acc = 0.0f;

    for (int i = tid; i < K * CC; i += 256) {
        int k = i / CC, ch = i % CC;
        float cnt = (float)g_counts[k];
        if (cnt < 1.0f) cnt = 1.0f;
        cn[k][ch] = g_sums[ch * K + k] / cnt;
    }
    __syncthreads();

    if (tid < K) {
        float s = 0.0f;
#pragma unroll
        for (int ch = 0; ch < CC; ch++) { float v = cn[tid][ch]; s += v * v; }
        float n = sqrtf(s);
        if (n < 1e-8f) n = 1e-8f;
        inv_norm[tid] = 1.0f / n;
    }
    __syncthreads();

    for (int i = tid; i < K * CC; i += 256) {
        int k = i / CC;
        cn[k][i % CC] *= inv_norm[k];
    }
    __syncthreads();

    float local = 0.0f;
    for (int pair = tid; pair < K * K; pair += 256) {
        int i = pair / K, j = pair % K;
        float s = 0.0f;
#pragma unroll
        for (int ch = 0; ch < CC; ch++) s += cn[i][ch] * cn[j][ch];
        local += (i == j) ? (1.0f - s) : fmaxf(s, 0.0f);
    }
#pragma unroll
    for (int o = 16; o > 0; o >>= 1) local += __shfl_xor_sync(0xFFFFFFFFu, local, o);
    if (lane == 0) atomicAdd(&acc, local);
    __syncthreads();
    if (tid == 0) *out = acc / (float)(K * K * K);

    // self-reset scratch for the next launch
    for (int i = tid; i < CC * K; i += 256) g_sums[i] = 0.0f;
    if (tid < K) g_counts[tid] = 0u;
}

extern "C" void kernel_launch(void* const* d_in, const int* in_sizes, int n_in,
                              void* d_out, int out_size) {
    const float* in  = (const float*)d_in[0];
    const int*   tgt = (const int*)d_in[1];
    float*       out = (float*)d_out;

    prep_kernel<<<NPIX / 8 / 256, 256>>>(tgt);
    acc_kernel<<<dim3(CHUNKS, CC), NT>>>(in);
    finalize_kernel<<<1, 256>>>(out);
}